// round 16
// baseline (speedup 1.0000x reference)
#include <cuda_runtime.h>
#include <cuda_bf16.h>

// Problem constants
#define KSZ   9
#define PAD   4
#define H     256
#define W     256
#define HO    248
#define WO    248
#define B     4
#define PLANE (H * W)

// Half-space pair enumeration (weight fp+fq folded into exp weight), 2-row
// output blocking. 128-thread blocks (tile 64x8) -> grid 512, all blocks
// resident at once (even SM load). Window loads via one hoisted row pointer.
#define TW    64
#define TH    8
#define SW    72           // cols tx0-4 .. tx0+67
#define SH    16           // rows ty0 .. ty0+15 (halo below only)
#define NTHR  128
#define PSTR  (SH * SW)    // plane stride in floats (1152)

#define GX    4
#define GY    32           // full 256 image rows
#define NBLK  (GX * GY * B)   // 512

// -100 * log2(e) : exp(-color/0.01) = 2^(color * NC1)
#define NC1   (-144.26950408889634f)
// log2(e)/9      : dist = 2^(-d2_spatial * DC)
#define DC    (1.4426950408889634f / 9.0f)

typedef unsigned long long ull;

static __device__ float        g_bsums[NBLK];
static __device__ unsigned int g_count = 0;

__device__ __forceinline__ float ex2f(float v) {
    float r;
    asm("ex2.approx.f32 %0, %1;" : "=f"(r) : "f"(v));
    return r;
}
// Transparent pack/unpack: ptxas can alias these to register pairs.
__device__ __forceinline__ ull pk(float lo, float hi) {
    union { float2 f; ull u; } v;
    v.f = make_float2(lo, hi);
    return v.u;
}
__device__ __forceinline__ void upk(ull v, float& lo, float& hi) {
    union { float2 f; ull u; } t;
    t.u = v;
    lo = t.f.x;
    hi = t.f.y;
}
// {hi(a), lo(b)} -- odd-offset packed pair (real movs: pair must be realigned)
__device__ __forceinline__ ull comb(ull a, ull b) {
    union { float2 f; ull u; } ua, ub, r;
    ua.u = a; ub.u = b;
    r.f = make_float2(ua.f.y, ub.f.x);
    return r.u;
}
__device__ __forceinline__ ull f2add(ull a, ull b) {
    ull r;
    asm("add.rn.f32x2 %0, %1, %2;" : "=l"(r) : "l"(a), "l"(b));
    return r;
}
__device__ __forceinline__ ull f2mul(ull a, ull b) {
    ull r;
    asm("mul.rn.f32x2 %0, %1, %2;" : "=l"(r) : "l"(a), "l"(b));
    return r;
}
__device__ __forceinline__ ull f2fma(ull a, ull b, ull c) {
    ull r;
    asm("fma.rn.f32x2 %0, %1, %2, %3;" : "=l"(r) : "l"(a), "l"(b), "l"(c));
    return r;
}

#define PACK_J(A_, J_) \
    ((((J_) & 1) == 0) ? A_[(J_) / 2] : comb(A_[((J_) - 1) / 2], A_[((J_) + 1) / 2]))

__global__ __launch_bounds__(NTHR, 4)
void potts_fused(const float* __restrict__ x, const float* __restrict__ y,
                 float* __restrict__ out) {
    __shared__ float s[5][SH][SW];   // x0,x1,x2,y0,y1 -> 23040 B

    const int b   = blockIdx.z;
    const int tx0 = blockIdx.x * TW;
    const int ty0 = blockIdx.y * TH;
    const int tid = threadIdx.x;

    const float* xb = x + (size_t)b * 3 * PLANE;
    const float* yb = y + (size_t)b * 2 * PLANE;

    // Halo fill. x: clamped. y: zeroed OUTSIDE the image.
    for (int i = tid; i < 5 * SH * SW; i += NTHR) {
        int p  = i / (SH * SW);
        int r  = (i / SW) % SH;
        int c  = i % SW;
        int uy = ty0 + r;
        int ux = tx0 - 4 + c;
        int gy = min(uy, H - 1);
        int gx = min(max(ux, 0), W - 1);
        float v;
        if (p < 3) {
            v = xb[p * PLANE + gy * W + gx];
        } else {
            v = yb[(p - 3) * PLANE + gy * W + gx];
            if ((unsigned)uy > 255u || (unsigned)ux > 255u) v = 0.0f;
        }
        s[p][r][c] = v;
    }
    __syncthreads();

    const int lane = tid & 31;
    const int w2   = (tid >> 5) * 2;    // warp = 2 output rows (0,2,4,6)
    const int lx2  = lane * 2;
    const int gr0  = ty0 + w2;
    const int gr1  = gr0 + 1;
    const int gc0  = tx0 + lx2;

    // Packed negated x centers, per output row
    const ull nA0 = pk(-s[0][w2][lx2 + 4],     -s[0][w2][lx2 + 5]);
    const ull nA1 = pk(-s[1][w2][lx2 + 4],     -s[1][w2][lx2 + 5]);
    const ull nA2 = pk(-s[2][w2][lx2 + 4],     -s[2][w2][lx2 + 5]);
    const ull nB0 = pk(-s[0][w2 + 1][lx2 + 4], -s[0][w2 + 1][lx2 + 5]);
    const ull nB1 = pk(-s[1][w2 + 1][lx2 + 4], -s[1][w2 + 1][lx2 + 5]);
    const ull nB2 = pk(-s[2][w2 + 1][lx2 + 4], -s[2][w2 + 1][lx2 + 5]);
    const float y0cA0 = s[3][w2][lx2 + 4],     y0cA1 = s[3][w2][lx2 + 5];
    const float y1cA0 = s[4][w2][lx2 + 4],     y1cA1 = s[4][w2][lx2 + 5];
    const float y0cB0 = s[3][w2 + 1][lx2 + 4], y0cB1 = s[3][w2 + 1][lx2 + 5];
    const float y1cB0 = s[4][w2 + 1][lx2 + 4], y1cB1 = s[4][w2 + 1][lx2 + 5];

    // fp per row/col
    const bool rIA = (unsigned)(gr0 - 4) <= 247u;
    const bool rIB = (unsigned)(gr1 - 4) <= 247u;
    const bool cI0 = (unsigned)(gc0 - 4) <= 247u;
    const bool cI1 = (unsigned)(gc0 - 3) <= 247u;
    const float fpA0 = (rIA && cI0) ? 1.0f : 0.0f;
    const float fpA1 = (rIA && cI1) ? 1.0f : 0.0f;
    const float fpB0 = (rIB && cI0) ? 1.0f : 0.0f;
    const float fpB1 = (rIB && cI1) ? 1.0f : 0.0f;
    const ull fpA = pk(fpA0, fpA1);
    const ull fpB = pk(fpB0, fpB1);

    // Packed column-interior masks (1.0f/0.0f) for q at col gc0+dj
    ull mj[9];
    #pragma unroll
    for (int j = 0; j < 9; j++) {
        const int cq = gc0 + j - 4;
        const float f0 = ((unsigned)(cq - 4) <= 247u) ? 1.0f : 0.0f;
        const float f1 = ((unsigned)(cq - 3) <= 247u) ? 1.0f : 0.0f;
        mj[j] = pk(f0, f1);
    }

    ull accAa = 0ull, accAb = 0ull;   // row0: Sum wt*y1q, Sum wt*y0q
    ull accBa = 0ull, accBb = 0ull;   // row1

    // One tap (window index J_); shared packs/mask, per-row color+exp+acc.
    // fq = mj*mrow (shared f2mul), then per row (fq+fp) and w*(...).
    #define TAP(J_, DJ_, EN0_, DI0_, EN1_, DI1_)                           \
    {                                                                      \
        const ull n0  = PACK_J(U0, J_);                                    \
        const ull n1  = PACK_J(U1, J_);                                    \
        const ull n2  = PACK_J(U2, J_);                                    \
        const ull qy0 = PACK_J(Q0, J_);                                    \
        const ull qy1 = PACK_J(Q1, J_);                                    \
        const ull mqf = f2mul(mj[(J_)], mrowp);                            \
        if (EN0_) {                                                        \
            ull d0 = f2add(n0, nA0);                                       \
            ull d1 = f2add(n1, nA1);                                       \
            ull d2 = f2add(n2, nA2);                                       \
            ull cc = f2mul(d0, d0);                                        \
            cc = f2fma(d1, d1, cc);                                        \
            cc = f2fma(d2, d2, cc);                                        \
            float clo, chi;                                                \
            upk(cc, clo, chi);                                             \
            const float ck = -(float)((DJ_)*(DJ_) + (DI0_)*(DI0_)) * DC;   \
            ull w  = pk(ex2f(fmaf(clo, NC1, ck)),                          \
                        ex2f(fmaf(chi, NC1, ck)));                         \
            ull wt = f2mul(w, f2add(mqf, fpA));                            \
            accAa = f2fma(wt, qy1, accAa);                                 \
            accAb = f2fma(wt, qy0, accAb);                                 \
        }                                                                  \
        if (EN1_) {                                                        \
            ull d0 = f2add(n0, nB0);                                       \
            ull d1 = f2add(n1, nB1);                                       \
            ull d2 = f2add(n2, nB2);                                       \
            ull cc = f2mul(d0, d0);                                        \
            cc = f2fma(d1, d1, cc);                                        \
            cc = f2fma(d2, d2, cc);                                        \
            float clo, chi;                                                \
            upk(cc, clo, chi);                                             \
            const float ck = -(float)((DJ_)*(DJ_) + (DI1_)*(DI1_)) * DC;   \
            ull w  = pk(ex2f(fmaf(clo, NC1, ck)),                          \
                        ex2f(fmaf(chi, NC1, ck)));                         \
            ull wt = f2mul(w, f2add(mqf, fpB));                            \
            accBa = f2fma(wt, qy1, accBa);                                 \
            accBb = f2fma(wt, qy0, accBb);                                 \
        }                                                                  \
    }

    // Window loads off ONE hoisted row pointer (constant plane offsets).
    #define LOAD_ROW(SR_)                                                  \
        ull U0[5], U1[5], U2[5], Q0[5], Q1[5];                             \
        {                                                                  \
            const float* rp = &s[0][(SR_)][lx2];                           \
            _Pragma("unroll")                                              \
            for (int m = 0; m < 5; m++) {                                  \
                U0[m] = *(const ull*)(rp + 2 * m);                         \
                U1[m] = *(const ull*)(rp + PSTR + 2 * m);                  \
                U2[m] = *(const ull*)(rp + 2 * PSTR + 2 * m);              \
                Q0[m] = *(const ull*)(rp + 3 * PSTR + 2 * m);              \
                Q1[m] = *(const ull*)(rp + 4 * PSTR + 2 * m);              \
            }                                                              \
        }                                                                  \
        const float rowf = ((unsigned)(gr0 + (SR_) - w2 - 4) <= 247u)      \
                               ? 1.0f : 0.0f;                              \
        const ull mrowp = pk(rowf, rowf);

    // it = sr - w2 = 0..5. row0 active it<=4 (di=it), row1 it>=1 (di=it-1).
    {   // it = 0: row0 di=0 (dj=1..4 only)
        LOAD_ROW(w2 + 0)
        TAP(5, 1, 1, 0, 0, 0) TAP(6, 2, 1, 0, 0, 0)
        TAP(7, 3, 1, 0, 0, 0) TAP(8, 4, 1, 0, 0, 0)
    }
    {   // it = 1: row0 di=1 (all taps); row1 di=0 (dj=1..4 only)
        LOAD_ROW(w2 + 1)
        TAP(0, -4, 1, 1, 0, 0) TAP(1, -3, 1, 1, 0, 0) TAP(2, -2, 1, 1, 0, 0)
        TAP(3, -1, 1, 1, 0, 0) TAP(4,  0, 1, 1, 0, 0)
        TAP(5,  1, 1, 1, 1, 0) TAP(6,  2, 1, 1, 1, 0)
        TAP(7,  3, 1, 1, 1, 0) TAP(8,  4, 1, 1, 1, 0)
    }
    {   // it = 2: row0 di=2, row1 di=1
        LOAD_ROW(w2 + 2)
        TAP(0, -4, 1, 2, 1, 1) TAP(1, -3, 1, 2, 1, 1) TAP(2, -2, 1, 2, 1, 1)
        TAP(3, -1, 1, 2, 1, 1) TAP(4,  0, 1, 2, 1, 1) TAP(5,  1, 1, 2, 1, 1)
        TAP(6,  2, 1, 2, 1, 1) TAP(7,  3, 1, 2, 1, 1) TAP(8,  4, 1, 2, 1, 1)
    }
    {   // it = 3: row0 di=3, row1 di=2
        LOAD_ROW(w2 + 3)
        TAP(0, -4, 1, 3, 1, 2) TAP(1, -3, 1, 3, 1, 2) TAP(2, -2, 1, 3, 1, 2)
        TAP(3, -1, 1, 3, 1, 2) TAP(4,  0, 1, 3, 1, 2) TAP(5,  1, 1, 3, 1, 2)
        TAP(6,  2, 1, 3, 1, 2) TAP(7,  3, 1, 3, 1, 2) TAP(8,  4, 1, 3, 1, 2)
    }
    {   // it = 4: row0 di=4, row1 di=3
        LOAD_ROW(w2 + 4)
        TAP(0, -4, 1, 4, 1, 3) TAP(1, -3, 1, 4, 1, 3) TAP(2, -2, 1, 4, 1, 3)
        TAP(3, -1, 1, 4, 1, 3) TAP(4,  0, 1, 4, 1, 3) TAP(5,  1, 1, 4, 1, 3)
        TAP(6,  2, 1, 4, 1, 3) TAP(7,  3, 1, 4, 1, 3) TAP(8,  4, 1, 4, 1, 3)
    }
    {   // it = 5: row1 di=4 only
        LOAD_ROW(w2 + 5)
        TAP(0, -4, 0, 0, 1, 4) TAP(1, -3, 0, 0, 1, 4) TAP(2, -2, 0, 0, 1, 4)
        TAP(3, -1, 0, 0, 1, 4) TAP(4,  0, 0, 0, 1, 4) TAP(5,  1, 0, 0, 1, 4)
        TAP(6,  2, 0, 0, 1, 4) TAP(7,  3, 0, 0, 1, 4) TAP(8,  4, 0, 0, 1, 4)
    }
    #undef TAP
    #undef LOAD_ROW

    float aA0, aA1, bA0, bA1, aB0, aB1, bB0, bB1;
    upk(accAa, aA0, aA1);
    upk(accAb, bA0, bA1);
    upk(accBa, aB0, aB1);
    upk(accBb, bB0, bB1);

    // per row/col: y0c*A + y1c*B + 2*fp*y0c*y1c
    float acc =
        fmaf(y0cA0, aA0, fmaf(y1cA0, bA0, 2.0f * fpA0 * y0cA0 * y1cA0)) +
        fmaf(y0cA1, aA1, fmaf(y1cA1, bA1, 2.0f * fpA1 * y0cA1 * y1cA1)) +
        fmaf(y0cB0, aB0, fmaf(y1cB0, bB0, 2.0f * fpB0 * y0cB0 * y1cB0)) +
        fmaf(y0cB1, aB1, fmaf(y1cB1, bB1, 2.0f * fpB1 * y0cB1 * y1cB1));

    // Deterministic block reduction
    #pragma unroll
    for (int off = 16; off > 0; off >>= 1)
        acc += __shfl_down_sync(0xffffffffu, acc, off);

    __shared__ float wsum[NTHR / 32];
    if (lane == 0) wsum[tid >> 5] = acc;
    __syncthreads();

    __shared__ bool is_last;
    if (tid == 0) {
        float t = 0.0f;
        #pragma unroll
        for (int i = 0; i < NTHR / 32; i++) t += wsum[i];
        const int bid = blockIdx.x + GX * (blockIdx.y + GY * blockIdx.z);
        g_bsums[bid] = t;
        __threadfence();
        unsigned int old = atomicAdd(&g_count, 1u);
        is_last = (old == (unsigned)(NBLK - 1));
    }
    __syncthreads();

    if (is_last) {
        __threadfence();
        double dacc = 0.0;
        for (int i = tid; i < NBLK; i += NTHR) dacc += (double)g_bsums[i];
        #pragma unroll
        for (int off = 16; off > 0; off >>= 1)
            dacc += __shfl_down_sync(0xffffffffu, dacc, off);
        __shared__ double dsum[NTHR / 32];
        if (lane == 0) dsum[tid >> 5] = dacc;
        __syncthreads();
        if (tid == 0) {
            double t = 0.0;
            #pragma unroll
            for (int i = 0; i < NTHR / 32; i++) t += dsum[i];
            const double scale = 1.0 / ((double)B * 81.0 * (double)HO * (double)WO);
            out[0] = (float)(t * scale);
            g_count = 0;   // reset for next graph replay
        }
    }
}

extern "C" void kernel_launch(void* const* d_in, const int* in_sizes, int n_in,
                              void* d_out, int out_size) {
    const float* x = (const float*)d_in[0];   // [4,3,256,256]
    const float* y = (const float*)d_in[1];   // [4,2,256,256]
    float* out = (float*)d_out;

    // Raise shared carveout so 4 blocks (92 KB) can be resident.
    cudaFuncSetAttribute(potts_fused,
                         cudaFuncAttributePreferredSharedMemoryCarveout,
                         cudaSharedmemCarveoutMaxShared);

    dim3 grid(GX, GY, B);
    potts_fused<<<grid, NTHR>>>(x, y, out);
}

// round 17
// speedup vs baseline: 1.3047x; 1.3047x over previous
#include <cuda_runtime.h>
#include <cuda_bf16.h>

// Problem constants
#define KSZ   9
#define PAD   4
#define H     256
#define W     256
#define HO    248
#define WO    248
#define B     4
#define PLANE (H * W)

// Half-space pair enumeration (weight fp+fq folded into exp weight), 2-row
// output blocking (R15 skeleton). Color term via dot-product form:
//   color = n2p + n2q - 2<xc,xq>,  with n2*NC1 precomputed into a smem plane.
#define TW    64
#define TH    16
#define SW    72           // cols tx0-4 .. tx0+67
#define SH    20           // rows ty0 .. ty0+19 (halo below only)
#define NTHR  256

#define GX    4
#define GY    16           // full 256 image rows
#define NBLK  (GX * GY * B)   // 256

// -100 * log2(e) : exp(-color/0.01) = 2^(color * NC1)
#define NC1   (-144.26950408889634f)
// -2 * NC1
#define M2S   (288.53900817779268f)
// log2(e)/9      : dist = 2^(-d2_spatial * DC)
#define DC    (1.4426950408889634f / 9.0f)

typedef unsigned long long ull;

static __device__ float        g_bsums[NBLK];
static __device__ unsigned int g_count = 0;

__device__ __forceinline__ float ex2f(float v) {
    float r;
    asm("ex2.approx.f32 %0, %1;" : "=f"(r) : "f"(v));
    return r;
}
__device__ __forceinline__ ull pk(float lo, float hi) {
    ull r;
    asm("mov.b64 %0, {%1, %2};" : "=l"(r) : "f"(lo), "f"(hi));
    return r;
}
__device__ __forceinline__ void upk(ull v, float& lo, float& hi) {
    asm("mov.b64 {%0, %1}, %2;" : "=f"(lo), "=f"(hi) : "l"(v));
}
// {hi(a), lo(b)} -- odd-offset packed pair from two adjacent aligned pairs
__device__ __forceinline__ ull comb(ull a, ull b) {
    ull r;
    asm("{\n\t"
        ".reg .b32 al, ah, bl, bh;\n\t"
        "mov.b64 {al, ah}, %1;\n\t"
        "mov.b64 {bl, bh}, %2;\n\t"
        "mov.b64 %0, {ah, bl};\n\t"
        "}" : "=l"(r) : "l"(a), "l"(b));
    return r;
}
__device__ __forceinline__ ull f2add(ull a, ull b) {
    ull r;
    asm("add.rn.f32x2 %0, %1, %2;" : "=l"(r) : "l"(a), "l"(b));
    return r;
}
__device__ __forceinline__ ull f2mul(ull a, ull b) {
    ull r;
    asm("mul.rn.f32x2 %0, %1, %2;" : "=l"(r) : "l"(a), "l"(b));
    return r;
}
__device__ __forceinline__ ull f2fma(ull a, ull b, ull c) {
    ull r;
    asm("fma.rn.f32x2 %0, %1, %2, %3;" : "=l"(r) : "l"(a), "l"(b), "l"(c));
    return r;
}

#define PACK_J(A_, J_) \
    ((((J_) & 1) == 0) ? A_[(J_) / 2] : comb(A_[((J_) - 1) / 2], A_[((J_) + 1) / 2]))

__global__ __launch_bounds__(NTHR, 2)
void potts_fused(const float* __restrict__ x, const float* __restrict__ y,
                 float* __restrict__ out) {
    // planes: 0,1,2 = x channels; 3 = (x0^2+x1^2+x2^2)*NC1; 4,5 = y (zeroed
    // outside image)
    __shared__ float s[6][SH][SW];   // 34560 B

    const int b   = blockIdx.z;
    const int tx0 = blockIdx.x * TW;
    const int ty0 = blockIdx.y * TH;
    const int tid = threadIdx.x;

    const float* xb = x + (size_t)b * 3 * PLANE;
    const float* yb = y + (size_t)b * 2 * PLANE;

    // Per-pixel fill: load 5 values, compute scaled norm once per pixel.
    for (int i = tid; i < SH * SW; i += NTHR) {
        int r  = i / SW;
        int c  = i % SW;
        int uy = ty0 + r;
        int ux = tx0 - 4 + c;
        int gy = min(uy, H - 1);
        int gx = min(max(ux, 0), W - 1);
        const int o = gy * W + gx;
        float x0 = xb[o], x1 = xb[PLANE + o], x2 = xb[2 * PLANE + o];
        float y0 = yb[o], y1 = yb[PLANE + o];
        if ((unsigned)uy > 255u || (unsigned)ux > 255u) { y0 = 0.0f; y1 = 0.0f; }
        s[0][r][c] = x0;
        s[1][r][c] = x1;
        s[2][r][c] = x2;
        s[3][r][c] = fmaf(x2, x2, fmaf(x1, x1, x0 * x0)) * NC1;
        s[4][r][c] = y0;
        s[5][r][c] = y1;
    }
    __syncthreads();

    const int lane = tid & 31;
    const int w2   = (tid >> 5) * 2;    // warp = 2 output rows
    const int lx2  = lane * 2;
    const int gr0  = ty0 + w2;
    const int gr1  = gr0 + 1;
    const int gc0  = tx0 + lx2;

    // Packed x centers (raw) and scaled-norm bases, per output row
    const ull cA0 = pk(s[0][w2][lx2 + 4],     s[0][w2][lx2 + 5]);
    const ull cA1 = pk(s[1][w2][lx2 + 4],     s[1][w2][lx2 + 5]);
    const ull cA2 = pk(s[2][w2][lx2 + 4],     s[2][w2][lx2 + 5]);
    const ull bseA = pk(s[3][w2][lx2 + 4],    s[3][w2][lx2 + 5]);
    const ull cB0 = pk(s[0][w2 + 1][lx2 + 4], s[0][w2 + 1][lx2 + 5]);
    const ull cB1 = pk(s[1][w2 + 1][lx2 + 4], s[1][w2 + 1][lx2 + 5]);
    const ull cB2 = pk(s[2][w2 + 1][lx2 + 4], s[2][w2 + 1][lx2 + 5]);
    const ull bseB = pk(s[3][w2 + 1][lx2 + 4], s[3][w2 + 1][lx2 + 5]);
    const float y0cA0 = s[4][w2][lx2 + 4],     y0cA1 = s[4][w2][lx2 + 5];
    const float y1cA0 = s[5][w2][lx2 + 4],     y1cA1 = s[5][w2][lx2 + 5];
    const float y0cB0 = s[4][w2 + 1][lx2 + 4], y0cB1 = s[4][w2 + 1][lx2 + 5];
    const float y1cB0 = s[5][w2 + 1][lx2 + 4], y1cB1 = s[5][w2 + 1][lx2 + 5];

    const ull M2 = pk(M2S, M2S);

    // fp per row/col
    const bool rIA = (unsigned)(gr0 - 4) <= 247u;
    const bool rIB = (unsigned)(gr1 - 4) <= 247u;
    const bool cI0 = (unsigned)(gc0 - 4) <= 247u;
    const bool cI1 = (unsigned)(gc0 - 3) <= 247u;
    const float fpA0 = (rIA && cI0) ? 1.0f : 0.0f;
    const float fpA1 = (rIA && cI1) ? 1.0f : 0.0f;
    const float fpB0 = (rIB && cI0) ? 1.0f : 0.0f;
    const float fpB1 = (rIB && cI1) ? 1.0f : 0.0f;
    const ull fpA = pk(fpA0, fpA1);
    const ull fpB = pk(fpB0, fpB1);

    // Packed column-interior masks (1.0f/0.0f) for q at col gc0+dj
    ull mj[9];
    #pragma unroll
    for (int j = 0; j < 9; j++) {
        const int cq = gc0 + j - 4;
        const float f0 = ((unsigned)(cq - 4) <= 247u) ? 1.0f : 0.0f;
        const float f1 = ((unsigned)(cq - 3) <= 247u) ? 1.0f : 0.0f;
        mj[j] = pk(f0, f1);
    }

    ull accAa = 0ull, accAb = 0ull;   // row0: Sum wt*y1q, Sum wt*y0q
    ull accBa = 0ull, accBb = 0ull;   // row1

    // One tap (window index J_); shared packs/mask, per-row dot+exp+acc.
    // arg = dot*(-2*NC1) + (n2q*NC1 + n2p*NC1); w = 2^(arg + ck).
    #define TAP(J_, DJ_, EN0_, DI0_, EN1_, DI1_)                           \
    {                                                                      \
        const ull n0  = PACK_J(U0, J_);                                    \
        const ull n1  = PACK_J(U1, J_);                                    \
        const ull n2  = PACK_J(U2, J_);                                    \
        const ull nn  = PACK_J(N2, J_);                                    \
        const ull qy0 = PACK_J(Q0, J_);                                    \
        const ull qy1 = PACK_J(Q1, J_);                                    \
        const ull mq  = mj[(J_)] & mrow;                                   \
        if (EN0_) {                                                        \
            ull dp = f2mul(n0, cA0);                                       \
            dp = f2fma(n1, cA1, dp);                                       \
            dp = f2fma(n2, cA2, dp);                                       \
            ull ag = f2fma(dp, M2, f2add(nn, bseA));                       \
            float alo, ahi;                                                \
            upk(ag, alo, ahi);                                             \
            const float ck = -(float)((DJ_)*(DJ_) + (DI0_)*(DI0_)) * DC;   \
            ull w  = pk(ex2f(alo + ck), ex2f(ahi + ck));                   \
            ull wt = f2mul(w, f2add(mq, fpA));                             \
            accAa = f2fma(wt, qy1, accAa);                                 \
            accAb = f2fma(wt, qy0, accAb);                                 \
        }                                                                  \
        if (EN1_) {                                                        \
            ull dp = f2mul(n0, cB0);                                       \
            dp = f2fma(n1, cB1, dp);                                       \
            dp = f2fma(n2, cB2, dp);                                       \
            ull ag = f2fma(dp, M2, f2add(nn, bseB));                       \
            float alo, ahi;                                                \
            upk(ag, alo, ahi);                                             \
            const float ck = -(float)((DJ_)*(DJ_) + (DI1_)*(DI1_)) * DC;   \
            ull w  = pk(ex2f(alo + ck), ex2f(ahi + ck));                   \
            ull wt = f2mul(w, f2add(mq, fpB));                             \
            accBa = f2fma(wt, qy1, accBa);                                 \
            accBb = f2fma(wt, qy0, accBb);                                 \
        }                                                                  \
    }

    #define LOAD_ROW(SR_)                                                  \
        ull U0[5], U1[5], U2[5], N2[5], Q0[5], Q1[5];                      \
        {                                                                  \
            const int sr = (SR_);                                          \
            _Pragma("unroll")                                              \
            for (int m = 0; m < 5; m++) {                                  \
                U0[m] = *(const ull*)&s[0][sr][lx2 + 2 * m];                \
                U1[m] = *(const ull*)&s[1][sr][lx2 + 2 * m];                \
                U2[m] = *(const ull*)&s[2][sr][lx2 + 2 * m];                \
                N2[m] = *(const ull*)&s[3][sr][lx2 + 2 * m];                \
                Q0[m] = *(const ull*)&s[4][sr][lx2 + 2 * m];                \
                Q1[m] = *(const ull*)&s[5][sr][lx2 + 2 * m];                \
            }                                                              \
        }                                                                  \
        const ull mrow = ((unsigned)(gr0 + (SR_) - w2 - 4) <= 247u) ? ~0ull : 0ull;

    // it = sr - w2 = 0..5. row0 active it<=4 (di=it), row1 it>=1 (di=it-1).
    {   // it = 0: row0 di=0 (dj=1..4 only)
        LOAD_ROW(w2 + 0)
        TAP(5, 1, 1, 0, 0, 0) TAP(6, 2, 1, 0, 0, 0)
        TAP(7, 3, 1, 0, 0, 0) TAP(8, 4, 1, 0, 0, 0)
    }
    {   // it = 1: row0 di=1 (all taps); row1 di=0 (dj=1..4 only)
        LOAD_ROW(w2 + 1)
        TAP(0, -4, 1, 1, 0, 0) TAP(1, -3, 1, 1, 0, 0) TAP(2, -2, 1, 1, 0, 0)
        TAP(3, -1, 1, 1, 0, 0) TAP(4,  0, 1, 1, 0, 0)
        TAP(5,  1, 1, 1, 1, 0) TAP(6,  2, 1, 1, 1, 0)
        TAP(7,  3, 1, 1, 1, 0) TAP(8,  4, 1, 1, 1, 0)
    }
    {   // it = 2: row0 di=2, row1 di=1
        LOAD_ROW(w2 + 2)
        TAP(0, -4, 1, 2, 1, 1) TAP(1, -3, 1, 2, 1, 1) TAP(2, -2, 1, 2, 1, 1)
        TAP(3, -1, 1, 2, 1, 1) TAP(4,  0, 1, 2, 1, 1) TAP(5,  1, 1, 2, 1, 1)
        TAP(6,  2, 1, 2, 1, 1) TAP(7,  3, 1, 2, 1, 1) TAP(8,  4, 1, 2, 1, 1)
    }
    {   // it = 3: row0 di=3, row1 di=2
        LOAD_ROW(w2 + 3)
        TAP(0, -4, 1, 3, 1, 2) TAP(1, -3, 1, 3, 1, 2) TAP(2, -2, 1, 3, 1, 2)
        TAP(3, -1, 1, 3, 1, 2) TAP(4,  0, 1, 3, 1, 2) TAP(5,  1, 1, 3, 1, 2)
        TAP(6,  2, 1, 3, 1, 2) TAP(7,  3, 1, 3, 1, 2) TAP(8,  4, 1, 3, 1, 2)
    }
    {   // it = 4: row0 di=4, row1 di=3
        LOAD_ROW(w2 + 4)
        TAP(0, -4, 1, 4, 1, 3) TAP(1, -3, 1, 4, 1, 3) TAP(2, -2, 1, 4, 1, 3)
        TAP(3, -1, 1, 4, 1, 3) TAP(4,  0, 1, 4, 1, 3) TAP(5,  1, 1, 4, 1, 3)
        TAP(6,  2, 1, 4, 1, 3) TAP(7,  3, 1, 4, 1, 3) TAP(8,  4, 1, 4, 1, 3)
    }
    {   // it = 5: row1 di=4 only
        LOAD_ROW(w2 + 5)
        TAP(0, -4, 0, 0, 1, 4) TAP(1, -3, 0, 0, 1, 4) TAP(2, -2, 0, 0, 1, 4)
        TAP(3, -1, 0, 0, 1, 4) TAP(4,  0, 0, 0, 1, 4) TAP(5,  1, 0, 0, 1, 4)
        TAP(6,  2, 0, 0, 1, 4) TAP(7,  3, 0, 0, 1, 4) TAP(8,  4, 0, 0, 1, 4)
    }
    #undef TAP
    #undef LOAD_ROW

    float aA0, aA1, bA0, bA1, aB0, aB1, bB0, bB1;
    upk(accAa, aA0, aA1);
    upk(accAb, bA0, bA1);
    upk(accBa, aB0, aB1);
    upk(accBb, bB0, bB1);

    // per row/col: y0c*A + y1c*B + 2*fp*y0c*y1c
    float acc =
        fmaf(y0cA0, aA0, fmaf(y1cA0, bA0, 2.0f * fpA0 * y0cA0 * y1cA0)) +
        fmaf(y0cA1, aA1, fmaf(y1cA1, bA1, 2.0f * fpA1 * y0cA1 * y1cA1)) +
        fmaf(y0cB0, aB0, fmaf(y1cB0, bB0, 2.0f * fpB0 * y0cB0 * y1cB0)) +
        fmaf(y0cB1, aB1, fmaf(y1cB1, bB1, 2.0f * fpB1 * y0cB1 * y1cB1));

    // Deterministic block reduction
    #pragma unroll
    for (int off = 16; off > 0; off >>= 1)
        acc += __shfl_down_sync(0xffffffffu, acc, off);

    __shared__ float wsum[NTHR / 32];
    if (lane == 0) wsum[tid >> 5] = acc;
    __syncthreads();

    __shared__ bool is_last;
    if (tid == 0) {
        float t = 0.0f;
        #pragma unroll
        for (int i = 0; i < NTHR / 32; i++) t += wsum[i];
        const int bid = blockIdx.x + GX * (blockIdx.y + GY * blockIdx.z);
        g_bsums[bid] = t;
        __threadfence();
        unsigned int old = atomicAdd(&g_count, 1u);
        is_last = (old == (unsigned)(NBLK - 1));
    }
    __syncthreads();

    if (is_last) {
        __threadfence();
        double dacc = 0.0;
        for (int i = tid; i < NBLK; i += NTHR) dacc += (double)g_bsums[i];
        #pragma unroll
        for (int off = 16; off > 0; off >>= 1)
            dacc += __shfl_down_sync(0xffffffffu, dacc, off);
        __shared__ double dsum[NTHR / 32];
        if (lane == 0) dsum[tid >> 5] = dacc;
        __syncthreads();
        if (tid == 0) {
            double t = 0.0;
            #pragma unroll
            for (int i = 0; i < NTHR / 32; i++) t += dsum[i];
            const double scale = 1.0 / ((double)B * 81.0 * (double)HO * (double)WO);
            out[0] = (float)(t * scale);
            g_count = 0;   // reset for next graph replay
        }
    }
}

extern "C" void kernel_launch(void* const* d_in, const int* in_sizes, int n_in,
                              void* d_out, int out_size) {
    const float* x = (const float*)d_in[0];   // [4,3,256,256]
    const float* y = (const float*)d_in[1];   // [4,2,256,256]
    float* out = (float*)d_out;

    // Raise shared carveout: 2 blocks x 34.6 KB = 69.1 KB.
    cudaFuncSetAttribute(potts_fused,
                         cudaFuncAttributePreferredSharedMemoryCarveout,
                         cudaSharedmemCarveoutMaxShared);

    dim3 grid(GX, GY, B);
    potts_fused<<<grid, NTHR>>>(x, y, out);
}